// round 2
// baseline (speedup 1.0000x reference)
#include <cuda_runtime.h>

#define Bq 4
#define Sq 2048
#define Dm 1024
#define Hh 16
#define DP 64
#define MTOK (Bq*Sq)          /* 8192 */
#define NBH  (Bq*Hh)          /* 64   */
#define OUT_ELEMS (MTOK*Dm)   /* 8388608 */

// Scratch (allocation-free rule: __device__ globals)
__device__ float g_q[(size_t)NBH*Sq*DP];
__device__ float g_k[(size_t)NBH*Sq*DP];
__device__ float g_v[(size_t)NBH*Sq*DP];
__device__ float g_rep[(size_t)MTOK*Dm];
__device__ float g_attn_fallback[(size_t)NBH*Sq*Sq];  // used only if harness out buffer lacks attn space

typedef unsigned long long ull;

__device__ __forceinline__ void fma2(ull& c, ull a, ull b) {
    asm("fma.rn.f32x2 %0, %1, %2, %0;" : "+l"(c) : "l"(a), "l"(b));
}
__device__ __forceinline__ ull dup2(float a) {
    ull r; asm("mov.b64 %0, {%1, %1};" : "=l"(r) : "f"(a)); return r;
}
__device__ __forceinline__ void unpack2(ull c, float& lo, float& hi) {
    asm("mov.b64 {%0, %1}, %2;" : "=f"(lo), "=f"(hi) : "l"(c));
}

// ---------------------------------------------------------------------------
// GEMM + bias: Y = X @ W + b.  X [8192,1024] row-major, W [1024,1024] (in,out).
// target 0/1/2 -> head-split store into g_q/g_k/g_v ; target 3 -> row-major to dout.
// Tile 128x128x16, 256 threads, 8x8 microtile, f32x2 FMAs.
// ---------------------------------------------------------------------------
__global__ __launch_bounds__(256) void gemm_bias_kernel(
    const float* __restrict__ X, const float* __restrict__ W,
    const float* __restrict__ bias, float* __restrict__ dout, int target)
{
    __shared__ __align__(16) float As[16][132];
    __shared__ __align__(16) float Bs[16][128];
    if (X == nullptr) X = g_rep;   // out-projection input

    const int tid = threadIdx.x;
    const int m0 = blockIdx.x * 128, n0 = blockIdx.y * 128;
    const int rb = (tid >> 4) * 8, cb = (tid & 15) * 8;

    ull acc[8][4];
#pragma unroll
    for (int i = 0; i < 8; i++)
#pragma unroll
        for (int j = 0; j < 4; j++) acc[i][j] = 0ull;

    for (int k0 = 0; k0 < Dm; k0 += 16) {
#pragma unroll
        for (int l = 0; l < 2; l++) {
            int idx = tid + l * 256;
            int r = idx >> 2, c4 = (idx & 3) * 4;
            float4 v = *(const float4*)&X[(size_t)(m0 + r) * Dm + k0 + c4];
            As[c4 + 0][r] = v.x; As[c4 + 1][r] = v.y;
            As[c4 + 2][r] = v.z; As[c4 + 3][r] = v.w;
        }
#pragma unroll
        for (int l = 0; l < 2; l++) {
            int idx = tid + l * 256;
            int r = idx >> 5, c = (idx & 31) * 4;
            *(float4*)&Bs[r][c] = *(const float4*)&W[(size_t)(k0 + r) * Dm + n0 + c];
        }
        __syncthreads();
#pragma unroll
        for (int kk = 0; kk < 16; kk++) {
            float a[8];
            *(float4*)(a)     = *(const float4*)&As[kk][rb];
            *(float4*)(a + 4) = *(const float4*)&As[kk][rb + 4];
            ull bb[4];
#pragma unroll
            for (int j = 0; j < 4; j++) bb[j] = *(const ull*)&Bs[kk][cb + 2 * j];
#pragma unroll
            for (int i = 0; i < 8; i++) {
                ull aa = dup2(a[i]);
#pragma unroll
                for (int j = 0; j < 4; j++) fma2(acc[i][j], aa, bb[j]);
            }
        }
        __syncthreads();
    }

    float* hs_out = (target == 0) ? g_q : (target == 1) ? g_k : g_v;
#pragma unroll
    for (int i = 0; i < 8; i++) {
        int m = m0 + rb + i;
        int bidx = m >> 11, sl = m & 2047;
#pragma unroll
        for (int j = 0; j < 4; j++) {
            int n = n0 + cb + 2 * j;
            float c0, c1; unpack2(acc[i][j], c0, c1);
            c0 += bias[n]; c1 += bias[n + 1];
            if (target < 3) {
                int h = n >> 6, dc = n & 63;
                float* p = hs_out + ((size_t)(bidx * Hh + h) * Sq + sl) * DP + dc;
                p[0] = c0; p[1] = c1;
            } else {
                float* p = dout + (size_t)m * Dm + n;
                p[0] = c0; p[1] = c1;
            }
        }
    }
}

// ---------------------------------------------------------------------------
// Scores: e = mask ? 0 : exp( (q . k) * 0.125 ).  Unnormalized, written to attn.
// Per (b,h) a [2048 x 2048 x 64] GEMM. Tile 128x128x16.
// ---------------------------------------------------------------------------
__global__ __launch_bounds__(256) void scores_kernel(
    const float* __restrict__ Mask, float* __restrict__ attn)
{
    __shared__ __align__(16) float As[16][132];
    __shared__ __align__(16) float Bs[16][132];
    const int tid = threadIdx.x;
    const int bh = blockIdx.z;
    const int b = bh >> 4;
    const int m0 = blockIdx.x * 128, n0 = blockIdx.y * 128;
    const float* Qp = g_q + (size_t)bh * Sq * DP;
    const float* Kp = g_k + (size_t)bh * Sq * DP;
    const int rb = (tid >> 4) * 8, cb = (tid & 15) * 8;

    ull acc[8][4];
#pragma unroll
    for (int i = 0; i < 8; i++)
#pragma unroll
        for (int j = 0; j < 4; j++) acc[i][j] = 0ull;

    for (int k0 = 0; k0 < DP; k0 += 16) {
#pragma unroll
        for (int l = 0; l < 2; l++) {
            int idx = tid + l * 256;
            int r = idx >> 2, c4 = (idx & 3) * 4;
            float4 v = *(const float4*)&Qp[(size_t)(m0 + r) * DP + k0 + c4];
            As[c4 + 0][r] = v.x; As[c4 + 1][r] = v.y;
            As[c4 + 2][r] = v.z; As[c4 + 3][r] = v.w;
            float4 w = *(const float4*)&Kp[(size_t)(n0 + r) * DP + k0 + c4];
            Bs[c4 + 0][r] = w.x; Bs[c4 + 1][r] = w.y;
            Bs[c4 + 2][r] = w.z; Bs[c4 + 3][r] = w.w;
        }
        __syncthreads();
#pragma unroll
        for (int kk = 0; kk < 16; kk++) {
            float a[8];
            *(float4*)(a)     = *(const float4*)&As[kk][rb];
            *(float4*)(a + 4) = *(const float4*)&As[kk][rb + 4];
            ull bb[4];
#pragma unroll
            for (int j = 0; j < 4; j++) bb[j] = *(const ull*)&Bs[kk][cb + 2 * j];
#pragma unroll
            for (int i = 0; i < 8; i++) {
                ull aa = dup2(a[i]);
#pragma unroll
                for (int j = 0; j < 4; j++) fma2(acc[i][j], aa, bb[j]);
            }
        }
        __syncthreads();
    }

    const float scale = 0.125f;
#pragma unroll
    for (int i = 0; i < 8; i++) {
        int qm = m0 + rb + i;
        const float* mrow = Mask + (size_t)(b * Sq + qm) * Sq;
        float* arow = attn + ((size_t)bh * Sq + qm) * Sq;
#pragma unroll
        for (int j = 0; j < 4; j++) {
            int kn = n0 + cb + 2 * j;
            float c0, c1; unpack2(acc[i][j], c0, c1);
            float2 mv = *(const float2*)&mrow[kn];
            float e0 = (mv.x != 0.0f) ? 0.0f : __expf(c0 * scale);
            float e1 = (mv.y != 0.0f) ? 0.0f : __expf(c1 * scale);
            float2 ev; ev.x = e0; ev.y = e1;
            *(float2*)&arow[kn] = ev;
        }
    }
}

// ---------------------------------------------------------------------------
// Row-normalize attn in place. One block (256 thr) per row of 2048.
// Row kept in registers: 1 read + 1 write.
// ---------------------------------------------------------------------------
__global__ __launch_bounds__(256) void norm_kernel(float* __restrict__ attn)
{
    __shared__ float red[256];
    const size_t row = blockIdx.x;
    float4* p = (float4*)(attn + row * Sq);
    const int t = threadIdx.x;
    float4 v0 = p[t], v1 = p[t + 256];
    float s = v0.x + v0.y + v0.z + v0.w + v1.x + v1.y + v1.z + v1.w;
    red[t] = s;
    __syncthreads();
    for (int o = 128; o > 0; o >>= 1) {
        if (t < o) red[t] += red[t + o];
        __syncthreads();
    }
    float inv = 1.0f / red[0];
    v0.x *= inv; v0.y *= inv; v0.z *= inv; v0.w *= inv;
    v1.x *= inv; v1.y *= inv; v1.z *= inv; v1.w *= inv;
    p[t] = v0; p[t + 256] = v1;
}

// ---------------------------------------------------------------------------
// rep = attn @ v per (b,h): [2048 x 64 x 2048]. Tile 128x64x16, micro 8x4.
// Writes g_rep in concat [B,S,D] layout.
// ---------------------------------------------------------------------------
__global__ __launch_bounds__(256) void av_kernel(const float* __restrict__ attn)
{
    __shared__ __align__(16) float As[16][132];
    __shared__ __align__(16) float Bs[16][64];
    const int tid = threadIdx.x;
    const int m0 = blockIdx.x * 128;
    const int bh = blockIdx.y;
    const int b = bh >> 4, h = bh & 15;
    const float* Ap = attn + (size_t)bh * Sq * Sq;
    const float* Vp = g_v + (size_t)bh * Sq * DP;
    const int rb = (tid >> 4) * 8, cb = (tid & 15) * 4;

    ull acc[8][2];
#pragma unroll
    for (int i = 0; i < 8; i++) { acc[i][0] = 0ull; acc[i][1] = 0ull; }

    for (int k0 = 0; k0 < Sq; k0 += 16) {
#pragma unroll
        for (int l = 0; l < 2; l++) {
            int idx = tid + l * 256;
            int r = idx >> 2, c4 = (idx & 3) * 4;
            float4 v = *(const float4*)&Ap[(size_t)(m0 + r) * Sq + k0 + c4];
            As[c4 + 0][r] = v.x; As[c4 + 1][r] = v.y;
            As[c4 + 2][r] = v.z; As[c4 + 3][r] = v.w;
        }
        {
            int r = tid >> 4, c = (tid & 15) * 4;
            *(float4*)&Bs[r][c] = *(const float4*)&Vp[(size_t)(k0 + r) * DP + c];
        }
        __syncthreads();
#pragma unroll
        for (int kk = 0; kk < 16; kk++) {
            float a[8];
            *(float4*)(a)     = *(const float4*)&As[kk][rb];
            *(float4*)(a + 4) = *(const float4*)&As[kk][rb + 4];
            ull b0 = *(const ull*)&Bs[kk][cb];
            ull b1 = *(const ull*)&Bs[kk][cb + 2];
#pragma unroll
            for (int i = 0; i < 8; i++) {
                ull aa = dup2(a[i]);
                fma2(acc[i][0], aa, b0);
                fma2(acc[i][1], aa, b1);
            }
        }
        __syncthreads();
    }

#pragma unroll
    for (int i = 0; i < 8; i++) {
        int m = m0 + rb + i;
        float* p = g_rep + (size_t)(b * Sq + m) * Dm + h * DP + cb;
        float c0, c1; unpack2(acc[i][0], c0, c1);
        p[0] = c0; p[1] = c1;
        unpack2(acc[i][1], c0, c1);
        p[2] = c0; p[3] = c1;
    }
}

// ---------------------------------------------------------------------------
extern "C" void kernel_launch(void* const* d_in, const int* in_sizes, int n_in,
                              void* d_out, int out_size)
{
    const float* Q    = (const float*)d_in[0];
    const float* K    = (const float*)d_in[1];
    const float* V    = (const float*)d_in[2];
    const float* Mask = (const float*)d_in[3];
    const float* Wq   = (const float*)d_in[4];
    const float* bq   = (const float*)d_in[5];
    const float* Wk   = (const float*)d_in[6];
    const float* bk   = (const float*)d_in[7];
    const float* Wv   = (const float*)d_in[8];
    const float* bv   = (const float*)d_in[9];
    const float* Wo   = (const float*)d_in[10];
    const float* bo   = (const float*)d_in[11];

    float* out = (float*)d_out;

    // attn part of the output if the buffer has room, else device scratch
    float* attn;
    const size_t attn_elems = (size_t)NBH * Sq * Sq;
    if ((size_t)out_size >= (size_t)OUT_ELEMS + attn_elems) {
        attn = out + OUT_ELEMS;
    } else {
        void* p = nullptr;
        cudaGetSymbolAddress(&p, g_attn_fallback);
        attn = (float*)p;
    }

    dim3 gProj(MTOK / 128, Dm / 128);            // 64 x 8
    gemm_bias_kernel<<<gProj, 256>>>(Q, Wq, bq, nullptr, 0);
    gemm_bias_kernel<<<gProj, 256>>>(K, Wk, bk, nullptr, 1);
    gemm_bias_kernel<<<gProj, 256>>>(V, Wv, bv, nullptr, 2);

    dim3 gScore(Sq / 128, Sq / 128, NBH);        // 16 x 16 x 64
    scores_kernel<<<gScore, 256>>>(Mask, attn);

    norm_kernel<<<NBH * Sq, 256>>>(attn);        // 131072 blocks

    dim3 gAV(Sq / 128, NBH);                     // 16 x 64
    av_kernel<<<gAV, 256>>>(attn);

    gemm_bias_kernel<<<gProj, 256>>>(nullptr, Wo, bo, out, 3);
}

// round 5
// speedup vs baseline: 2.1654x; 2.1654x over previous
#include <cuda_runtime.h>
#include <cuda_fp16.h>
#include <cstdint>
#include <cstddef>

typedef unsigned int u32;

#define Bq 4
#define Sq 2048
#define Dm 1024
#define Hh 16
#define DP 64
#define MTOK (Bq*Sq)          /* 8192 */
#define NBH  (Bq*Hh)          /* 64   */
#define OUT_ELEMS (MTOK*Dm)   /* 8388608 */

// Scratch (allocation-free rule: __device__ globals)
__device__ float g_q[(size_t)NBH*Sq*DP];
__device__ float g_k[(size_t)NBH*Sq*DP];
__device__ float g_v[(size_t)NBH*Sq*DP];
__device__ float g_rep[(size_t)MTOK*Dm];
__device__ float g_rowsum[(size_t)NBH*Sq];
__device__ float g_attn_fallback[(size_t)NBH*Sq*Sq];

// ---------------------------------------------------------------------------
// helpers
// ---------------------------------------------------------------------------
__device__ __forceinline__ u32 saddr(const void* p) {
    return (u32)__cvta_generic_to_shared(p);
}
__device__ __forceinline__ u32 hpair(float a, float b) {
    __half2 t = __floats2half2_rn(a, b);
    return *reinterpret_cast<u32*>(&t);
}
// one fp32 -> (hi, lo) fp16 pair packed in one word (k-interleaved split)
__device__ __forceinline__ u32 splitw(float x) {
    float h = __half2float(__float2half_rn(x));
    return hpair(x, x - h);
}

__device__ __forceinline__ void mma16816(float* c, const u32* a, const u32* b) {
    asm volatile(
        "mma.sync.aligned.m16n8k16.row.col.f32.f16.f16.f32 "
        "{%0,%1,%2,%3},{%4,%5,%6,%7},{%8,%9},{%0,%1,%2,%3};"
        : "+f"(c[0]), "+f"(c[1]), "+f"(c[2]), "+f"(c[3])
        : "r"(a[0]), "r"(a[1]), "r"(a[2]), "r"(a[3]), "r"(b[0]), "r"(b[1]));
}
__device__ __forceinline__ void ldsm4(u32* r, u32 a) {
    asm volatile("ldmatrix.sync.aligned.m8n8.x4.shared.b16 {%0,%1,%2,%3},[%4];"
                 : "=r"(r[0]), "=r"(r[1]), "=r"(r[2]), "=r"(r[3]) : "r"(a));
}
__device__ __forceinline__ void ldsm4t(u32* r, u32 a) {
    asm volatile("ldmatrix.sync.aligned.m8n8.x4.trans.shared.b16 {%0,%1,%2,%3},[%4];"
                 : "=r"(r[0]), "=r"(r[1]), "=r"(r[2]), "=r"(r[3]) : "r"(a));
}

#define PAW 36   /* A row pitch in u32 words (72 fp16 = 144B, 16B-mult) */
#define PBW 68   /* proj B row pitch in u32 words (136 fp16 = 272B) */

__global__ void zero_rowsum_kernel() {
    int i = blockIdx.x * 256 + threadIdx.x;
    g_rowsum[i] = 0.0f;
}

// ---------------------------------------------------------------------------
// Projection GEMM: Y = X @ W + b, M=8192 N=1024 K=1024
// split-fp16 K-doubled: A rows pack [h,l]; B K'-rows duplicate [h,h].
// Block 128x128, 8 warps (2x4), warp tile 64x32.
// target 0/1/2 -> head-split to g_q/g_k/g_v ; 3 -> row-major to dout.
// ---------------------------------------------------------------------------
__global__ __launch_bounds__(256) void proj_mma(
    const float* __restrict__ X, const float* __restrict__ W,
    const float* __restrict__ bias, float* __restrict__ dout, int target)
{
    __shared__ __align__(16) u32 As[128 * PAW];   // [m][k'/2 words]
    __shared__ __align__(16) u32 Bs[64 * PBW];    // [k'][n/2 words]
    if (X == nullptr) X = g_rep;

    const int tid = threadIdx.x;
    const int m0 = blockIdx.x * 128, n0 = blockIdx.y * 128;
    const int warp = tid >> 5, lane = tid & 31;
    const int wm = (warp >> 2) * 64, wn = (warp & 3) * 32;
    const int g = lane >> 2, tig = lane & 3;

    const int a_row = (lane & 7) + ((lane >> 3) & 1) * 8;
    const int a_k   = (lane >> 4) * 8;
    const int bt_k  = (lane & 7) + ((lane >> 3) & 1) * 8;
    const int bt_n  = (lane >> 4) * 8;

    const u32 as_base = saddr(As), bs_base = saddr(Bs);

    float acc[4][4][4];
#pragma unroll
    for (int i = 0; i < 4; i++) {
#pragma unroll
        for (int j = 0; j < 4; j++) {
#pragma unroll
            for (int r = 0; r < 4; r++) { acc[i][j][r] = 0.0f; }
        }
    }

    for (int k0 = 0; k0 < Dm; k0 += 32) {
#pragma unroll
        for (int l = 0; l < 4; l++) {
            int idx = tid + l * 256;
            int r = idx >> 3, kq = idx & 7;
            float4 v = *(const float4*)&X[(size_t)(m0 + r) * Dm + k0 + kq * 4];
            uint4 w;
            w.x = splitw(v.x); w.y = splitw(v.y);
            w.z = splitw(v.z); w.w = splitw(v.w);
            *(uint4*)&As[r * PAW + kq * 4] = w;
        }
#pragma unroll
        for (int l = 0; l < 4; l++) {
            int idx = tid + l * 256;
            int r = idx >> 5, nq = idx & 31;
            float4 v = *(const float4*)&W[(size_t)(k0 + r) * Dm + n0 + nq * 4];
            uint2 dh;
            dh.x = hpair(v.x, v.y); dh.y = hpair(v.z, v.w);
            *(uint2*)&Bs[(2 * r) * PBW + nq * 2] = dh;       // hi
            *(uint2*)&Bs[(2 * r + 1) * PBW + nq * 2] = dh;   // hi again
        }
        __syncthreads();
#pragma unroll
        for (int ks = 0; ks < 64; ks += 16) {
            u32 af[4][4];
#pragma unroll
            for (int mi = 0; mi < 4; mi++) {
                ldsm4(af[mi], as_base + (u32)((wm + mi * 16 + a_row) * PAW + ((ks + a_k) >> 1)) * 4u);
            }
            u32 bf[2][4];
#pragma unroll
            for (int h = 0; h < 2; h++) {
                ldsm4t(bf[h], bs_base + (u32)((ks + bt_k) * PBW + ((wn + h * 16 + bt_n) >> 1)) * 4u);
            }
#pragma unroll
            for (int mi = 0; mi < 4; mi++) {
#pragma unroll
                for (int j = 0; j < 4; j++) {
                    mma16816(acc[mi][j], af[mi], &bf[j >> 1][(j & 1) * 2]);
                }
            }
        }
        __syncthreads();
    }

    float* hs_out = (target == 0) ? g_q : (target == 1) ? g_k : g_v;
#pragma unroll
    for (int mi = 0; mi < 4; mi++) {
        int row = m0 + wm + mi * 16 + g;
        int row2 = row + 8;
#pragma unroll
        for (int j = 0; j < 4; j++) {
            int col = n0 + wn + j * 8 + tig * 2;
            float b0 = bias[col], b1 = bias[col + 1];
            float2 v0 = make_float2(acc[mi][j][0] + b0, acc[mi][j][1] + b1);
            float2 v1 = make_float2(acc[mi][j][2] + b0, acc[mi][j][3] + b1);
            if (target < 3) {
                int h = col >> 6, dc = col & 63;
                int bi = row >> 11, sl = row & 2047;
                int bi2 = row2 >> 11, sl2 = row2 & 2047;
                *(float2*)&hs_out[((size_t)(bi * Hh + h) * Sq + sl) * DP + dc] = v0;
                *(float2*)&hs_out[((size_t)(bi2 * Hh + h) * Sq + sl2) * DP + dc] = v1;
            } else {
                *(float2*)&dout[(size_t)row * Dm + col] = v0;
                *(float2*)&dout[(size_t)row2 * Dm + col] = v1;
            }
        }
    }
}

// ---------------------------------------------------------------------------
// Scores: e = mask ? 0 : exp(0.125 * q.k). Unnormalized to attn + row sums.
// Per (b,h): M=N=2048 K=64. Block 128x128, warps 2x4.
// A(Q) packs [h,l]; B(K) packs [h,h] along k'.
// ---------------------------------------------------------------------------
__global__ __launch_bounds__(256) void scores_mma(
    const float* __restrict__ Mask, float* __restrict__ attn)
{
    __shared__ __align__(16) u32 As[128 * PAW];
    __shared__ __align__(16) u32 Bs[128 * PAW];
    const int tid = threadIdx.x;
    const int bh = blockIdx.z, b = bh >> 4;
    const int m0 = blockIdx.x * 128, n0 = blockIdx.y * 128;
    const float* Qp = g_q + (size_t)bh * Sq * DP;
    const float* Kp = g_k + (size_t)bh * Sq * DP;
    const int warp = tid >> 5, lane = tid & 31;
    const int wm = (warp >> 2) * 64, wn = (warp & 3) * 32;
    const int g = lane >> 2, tig = lane & 3;

    const int a_row = (lane & 7) + ((lane >> 3) & 1) * 8;
    const int a_k   = (lane >> 4) * 8;
    const int bn_n  = (lane & 7) + (lane >> 4) * 8;     // no-trans B: n row
    const int bn_k  = ((lane >> 3) & 1) * 8;            // no-trans B: k' offset

    const u32 as_base = saddr(As), bs_base = saddr(Bs);

    float acc[4][4][4];
#pragma unroll
    for (int i = 0; i < 4; i++) {
#pragma unroll
        for (int j = 0; j < 4; j++) {
#pragma unroll
            for (int r = 0; r < 4; r++) { acc[i][j][r] = 0.0f; }
        }
    }

    for (int k0 = 0; k0 < DP; k0 += 32) {
#pragma unroll
        for (int l = 0; l < 4; l++) {
            int idx = tid + l * 256;
            int r = idx >> 3, kq = idx & 7;
            float4 v = *(const float4*)&Qp[(size_t)(m0 + r) * DP + k0 + kq * 4];
            uint4 w;
            w.x = splitw(v.x); w.y = splitw(v.y);
            w.z = splitw(v.z); w.w = splitw(v.w);
            *(uint4*)&As[r * PAW + kq * 4] = w;
            float4 v2 = *(const float4*)&Kp[(size_t)(n0 + r) * DP + k0 + kq * 4];
            uint4 w2;
            w2.x = hpair(v2.x, v2.x); w2.y = hpair(v2.y, v2.y);
            w2.z = hpair(v2.z, v2.z); w2.w = hpair(v2.w, v2.w);
            *(uint4*)&Bs[r * PAW + kq * 4] = w2;
        }
        __syncthreads();
#pragma unroll
        for (int ks = 0; ks < 64; ks += 16) {
            u32 af[4][4];
#pragma unroll
            for (int mi = 0; mi < 4; mi++) {
                ldsm4(af[mi], as_base + (u32)((wm + mi * 16 + a_row) * PAW + ((ks + a_k) >> 1)) * 4u);
            }
            u32 bf[2][4];
#pragma unroll
            for (int h = 0; h < 2; h++) {
                ldsm4(bf[h], bs_base + (u32)((wn + h * 16 + bn_n) * PAW + ((ks + bn_k) >> 1)) * 4u);
            }
#pragma unroll
            for (int mi = 0; mi < 4; mi++) {
#pragma unroll
                for (int j = 0; j < 4; j++) {
                    mma16816(acc[mi][j], af[mi], &bf[j >> 1][(j & 1) * 2]);
                }
            }
        }
        __syncthreads();
    }

    const float scale = 0.125f;
#pragma unroll
    for (int mi = 0; mi < 4; mi++) {
        int r0 = m0 + wm + mi * 16 + g;
        int r1 = r0 + 8;
        const float* mr0 = Mask + ((size_t)b * Sq + r0) * Sq;
        const float* mr1 = Mask + ((size_t)b * Sq + r1) * Sq;
        float* ar0 = attn + ((size_t)bh * Sq + r0) * Sq;
        float* ar1 = attn + ((size_t)bh * Sq + r1) * Sq;
        float rs0 = 0.0f, rs1 = 0.0f;
#pragma unroll
        for (int j = 0; j < 4; j++) {
            int col = n0 + wn + j * 8 + tig * 2;
            float2 mv0 = *(const float2*)&mr0[col];
            float2 mv1 = *(const float2*)&mr1[col];
            float e00 = (mv0.x != 0.0f) ? 0.0f : __expf(acc[mi][j][0] * scale);
            float e01 = (mv0.y != 0.0f) ? 0.0f : __expf(acc[mi][j][1] * scale);
            float e10 = (mv1.x != 0.0f) ? 0.0f : __expf(acc[mi][j][2] * scale);
            float e11 = (mv1.y != 0.0f) ? 0.0f : __expf(acc[mi][j][3] * scale);
            *(float2*)&ar0[col] = make_float2(e00, e01);
            *(float2*)&ar1[col] = make_float2(e10, e11);
            rs0 += e00 + e01;
            rs1 += e10 + e11;
        }
        rs0 += __shfl_xor_sync(0xffffffffu, rs0, 1);
        rs0 += __shfl_xor_sync(0xffffffffu, rs0, 2);
        rs1 += __shfl_xor_sync(0xffffffffu, rs1, 1);
        rs1 += __shfl_xor_sync(0xffffffffu, rs1, 2);
        if (tig == 0) {
            atomicAdd(&g_rowsum[(size_t)bh * Sq + r0], rs0);
            atomicAdd(&g_rowsum[(size_t)bh * Sq + r1], rs1);
        }
    }
}

// ---------------------------------------------------------------------------
// AV: rep = softmax(attn) @ v. Normalizes attn IN PLACE during its only read.
// Per (b,h): M=2048 N=64 K=2048. Block 128x64, warps 4x2.
// A(attn) packs [h,l]; B(V) K'-rows duplicate [h,h].
// ---------------------------------------------------------------------------
__global__ __launch_bounds__(256) void av_mma(float* __restrict__ attn)
{
    __shared__ __align__(16) u32 As[128 * PAW];
    __shared__ __align__(16) u32 Bs[64 * PAW];
    __shared__ float inv_s[128];
    const int tid = threadIdx.x;
    const int bh = blockIdx.y, b = bh >> 4, h = bh & 15;
    const int m0 = blockIdx.x * 128;
    const float* Vp = g_v + (size_t)bh * Sq * DP;
    float* Ap = attn + (size_t)bh * Sq * Sq;
    const int warp = tid >> 5, lane = tid & 31;
    const int wm = (warp >> 1) * 32, wn = (warp & 1) * 32;
    const int g = lane >> 2, tig = lane & 3;

    const int a_row = (lane & 7) + ((lane >> 3) & 1) * 8;
    const int a_k   = (lane >> 4) * 8;
    const int bt_k  = (lane & 7) + ((lane >> 3) & 1) * 8;
    const int bt_n  = (lane >> 4) * 8;

    const u32 as_base = saddr(As), bs_base = saddr(Bs);

    if (tid < 128) { inv_s[tid] = 1.0f / g_rowsum[(size_t)bh * Sq + m0 + tid]; }
    __syncthreads();

    float acc[2][4][4];
#pragma unroll
    for (int i = 0; i < 2; i++) {
#pragma unroll
        for (int j = 0; j < 4; j++) {
#pragma unroll
            for (int r = 0; r < 4; r++) { acc[i][j][r] = 0.0f; }
        }
    }

    for (int k0 = 0; k0 < Sq; k0 += 32) {
#pragma unroll
        for (int l = 0; l < 4; l++) {
            int idx = tid + l * 256;
            int r = idx >> 3, kq = idx & 7;
            float* p = &Ap[(size_t)(m0 + r) * Sq + k0 + kq * 4];
            float4 v = *(const float4*)p;
            float iv = inv_s[r];
            *(float4*)p = make_float4(v.x * iv, v.y * iv, v.z * iv, v.w * iv);
            uint4 w;
            w.x = splitw(v.x); w.y = splitw(v.y);
            w.z = splitw(v.z); w.w = splitw(v.w);
            *(uint4*)&As[r * PAW + kq * 4] = w;
        }
#pragma unroll
        for (int l = 0; l < 2; l++) {
            int idx = tid + l * 256;
            int r = idx >> 4, nq = idx & 15;
            float4 v = *(const float4*)&Vp[(size_t)(k0 + r) * DP + nq * 4];
            uint2 dh;
            dh.x = hpair(v.x, v.y); dh.y = hpair(v.z, v.w);
            *(uint2*)&Bs[(2 * r) * PAW + nq * 2] = dh;       // hi
            *(uint2*)&Bs[(2 * r + 1) * PAW + nq * 2] = dh;   // hi again
        }
        __syncthreads();
#pragma unroll
        for (int ks = 0; ks < 64; ks += 16) {
            u32 af[2][4];
#pragma unroll
            for (int mi = 0; mi < 2; mi++) {
                ldsm4(af[mi], as_base + (u32)((wm + mi * 16 + a_row) * PAW + ((ks + a_k) >> 1)) * 4u);
            }
            u32 bf[2][4];
#pragma unroll
            for (int hh = 0; hh < 2; hh++) {
                ldsm4t(bf[hh], bs_base + (u32)((ks + bt_k) * PAW + ((wn + hh * 16 + bt_n) >> 1)) * 4u);
            }
#pragma unroll
            for (int mi = 0; mi < 2; mi++) {
#pragma unroll
                for (int j = 0; j < 4; j++) {
                    mma16816(acc[mi][j], af[mi], &bf[j >> 1][(j & 1) * 2]);
                }
            }
        }
        __syncthreads();
    }

#pragma unroll
    for (int mi = 0; mi < 2; mi++) {
        int row = m0 + wm + mi * 16 + g;
        int row2 = row + 8;
        float iv0 = inv_s[row - m0], iv1 = inv_s[row2 - m0];
#pragma unroll
        for (int j = 0; j < 4; j++) {
            int col = wn + j * 8 + tig * 2;
            float2 v0 = make_float2(acc[mi][j][0] * iv0, acc[mi][j][1] * iv0);
            float2 v1 = make_float2(acc[mi][j][2] * iv1, acc[mi][j][3] * iv1);
            *(float2*)&g_rep[(size_t)(b * Sq + row) * Dm + h * DP + col] = v0;
            *(float2*)&g_rep[(size_t)(b * Sq + row2) * Dm + h * DP + col] = v1;
        }
    }
}

// ---------------------------------------------------------------------------
extern "C" void kernel_launch(void* const* d_in, const int* in_sizes, int n_in,
                              void* d_out, int out_size)
{
    const float* Q    = (const float*)d_in[0];
    const float* K    = (const float*)d_in[1];
    const float* V    = (const float*)d_in[2];
    const float* Mask = (const float*)d_in[3];
    const float* Wq   = (const float*)d_in[4];
    const float* bq   = (const float*)d_in[5];
    const float* Wk   = (const float*)d_in[6];
    const float* bk   = (const float*)d_in[7];
    const float* Wv   = (const float*)d_in[8];
    const float* bv   = (const float*)d_in[9];
    const float* Wo   = (const float*)d_in[10];
    const float* bo   = (const float*)d_in[11];

    float* out = (float*)d_out;

    float* attn;
    const size_t attn_elems = (size_t)NBH * Sq * Sq;
    if ((size_t)out_size >= (size_t)OUT_ELEMS + attn_elems) {
        attn = out + OUT_ELEMS;
    } else {
        void* p = nullptr;
        cudaGetSymbolAddress(&p, g_attn_fallback);
        attn = (float*)p;
    }

    zero_rowsum_kernel<<<(NBH * Sq) / 256, 256>>>();

    dim3 gProj(MTOK / 128, Dm / 128);            // 64 x 8
    proj_mma<<<gProj, 256>>>(Q, Wq, bq, nullptr, 0);
    proj_mma<<<gProj, 256>>>(K, Wk, bk, nullptr, 1);
    proj_mma<<<gProj, 256>>>(V, Wv, bv, nullptr, 2);

    dim3 gScore(Sq / 128, Sq / 128, NBH);        // 16 x 16 x 64
    scores_mma<<<gScore, 256>>>(Mask, attn);

    dim3 gAV(Sq / 128, NBH);                     // 16 x 64
    av_mma<<<gAV, 256>>>(attn);

    proj_mma<<<gProj, 256>>>(nullptr, Wo, bo, out, 3);
}